// round 15
// baseline (speedup 1.0000x reference)
#include <cuda_runtime.h>
#include <math.h>

// Problem constants
#define PN   4096
#define TT   128
#define AA   32
#define KEL  409          // int(4096 * 0.1)
#define KPAD 512          // 32 warps * 16 elites, zero-weight padded
#define INFF 1e30f

// ---------------- scratch (no allocations allowed) ----------------
__device__ float g_dists[PN];
__device__ int   g_eidx[KEL];      // elite indices, rank order (top_k order)
__device__ float g_edist[KEL];     // elite dists, rank order
__device__ int   g_sidx[KPAD];     // elite indices sorted ASCENDING BY INDEX
__device__ float g_sw[KPAD];       // weights permuted to match g_sidx
__device__ float g_scalars[2];     // [0] = ssum, [1] = 1/(ssum+1e-9)

// =====================================================================
// Kernel A: DTW min-plus DP, one warp per problem (EXACT R13 version —
// the empirically fastest config; frozen).
// =====================================================================
__global__ void __launch_bounds__(256) dtw_kernel(const float* __restrict__ obs) {
    const unsigned FULL = 0xffffffffu;
    int warpId = (blockIdx.x * blockDim.x + threadIdx.x) >> 5;
    int lane   = threadIdx.x & 31;
    if (warpId >= PN) return;

    const float4* cbase = (const float4*)(obs + (size_t)warpId * TT * TT);

    float v0 = INFF, v1 = INFF, v2 = INFF, v3 = INFF;
    float carry = 0.0f;

    float4 c0 = __ldcs(cbase + lane);
    float s0 = c0.x;
    float s1 = s0 + c0.y;
    float s2 = s1 + c0.z;
    float s3 = s2 + c0.w;
    {
        float sum = s3;
        #pragma unroll
        for (int off = 1; off < 32; off <<= 1) {
            float t = __shfl_up_sync(FULL, sum, off);
            if (lane >= off) sum += t;
        }
        float base0 = sum - s3;
        s0 += base0; s1 += base0; s2 += base0; s3 += base0;
        c0.x = base0;
    }
    float base = c0.x;

    float4 cn = __ldcs(cbase + 32 + lane);

    #pragma unroll 2
    for (int i = 0; i < TT; i++) {
        int nl = (i + 2 < TT) ? (i + 2) : (TT - 1);
        float4 cf = __ldcs(cbase + nl * 32 + lane);

        float ns0 = cn.x;
        float ns1 = ns0 + cn.y;
        float ns2 = ns1 + cn.z;
        float ns3 = ns2 + cn.w;

        float up  = __shfl_up_sync(FULL, v3, 1);
        float sh0 = (lane == 0) ? carry : up;

        float m0 = fminf(v0, sh0);
        float m1 = fminf(v1, v0);
        float m2 = fminf(v2, v1);
        float m3 = fminf(v3, v2);

        float t0 = m0 - base;
        float t1 = m1 - s0;
        float t2 = m2 - s1;
        float t3 = m3 - s2;

        float p0 = t0;
        float p1 = fminf(p0, t1);
        float p2 = fminf(p1, t2);
        float p3 = fminf(p2, t3);

        float nsum = ns3;
        float mn   = p3;
        #pragma unroll
        for (int off = 1; off < 32; off <<= 1) {
            float ta = __shfl_up_sync(FULL, nsum, off);
            float tb = __shfl_up_sync(FULL, mn, off);
            if (lane >= off) {
                nsum += ta;
                mn    = fminf(mn, tb);
            }
        }

        float ex = __shfl_up_sync(FULL, mn, 1);
        if (lane == 0) ex = INFF;

        float nbase = nsum - ns3;

        v0 = s0 + fminf(p0, ex);
        v1 = s1 + fminf(p1, ex);
        v2 = s2 + fminf(p2, ex);
        v3 = s3 + fminf(p3, ex);

        base = nbase;
        s0 = ns0 + nbase;
        s1 = ns1 + nbase;
        s2 = ns2 + nbase;
        s3 = ns3 + nbase;
        carry = INFF;
        cn = cf;
    }

    if (lane == 31) g_dists[warpId] = v3;
}

// =====================================================================
// Kernel B: exact top-K selection via rank counting (unchanged).
// =====================================================================
__global__ void __launch_bounds__(256) rank_kernel() {
    __shared__ float sd[PN];
    for (int i = threadIdx.x; i < PN; i += blockDim.x) sd[i] = g_dists[i];
    __syncthreads();

    int warp = threadIdx.x >> 5;
    int lane = threadIdx.x & 31;

    #pragma unroll
    for (int e = 0; e < 4; e++) {
        int p = blockIdx.x * 32 + warp * 4 + e;
        float d = sd[p];
        int cnt = 0;
        #pragma unroll 4
        for (int j = lane; j < PN; j += 32) {
            float dj = sd[j];
            cnt += (dj < d) || (dj == d && j < p);
        }
        #pragma unroll
        for (int off = 16; off; off >>= 1)
            cnt += __shfl_down_sync(0xffffffffu, cnt, off);
        if (lane == 0 && cnt < KEL) {
            g_eidx[cnt]  = p;
            g_edist[cnt] = d;
        }
    }
}

// =====================================================================
// Kernel C: softmax elite scores + INDEX-SORTED re-emission (padded to
// 512 zero-weight slots so stats warps get exactly 16 elites each).
// =====================================================================
__global__ void __launch_bounds__(512) score_kernel() {
    __shared__ float sred[512];
    __shared__ unsigned mask[PN / 32];   // 128 words
    __shared__ int wordpfx[PN / 32];     // exclusive popcount prefix
    int tid = threadIdx.x;

    float d = (tid < KEL) ? g_edist[tid] : INFF;
    int   idx = (tid < KEL) ? g_eidx[tid] : 0;

    if (tid < PN / 32) mask[tid] = 0u;

    // min reduce
    sred[tid] = d; __syncthreads();
    #pragma unroll
    for (int s = 256; s; s >>= 1) {
        if (tid < s) sred[tid] = fminf(sred[tid], sred[tid + s]);
        __syncthreads();
    }
    float mind = sred[0]; __syncthreads();

    float e = (tid < KEL) ? expf(0.5f * (mind - d)) : 0.0f;

    // sum reduce of e; also build the elite index bitmask
    sred[tid] = e;
    if (tid < KEL) atomicOr(&mask[idx >> 5], 1u << (idx & 31));
    __syncthreads();
    #pragma unroll
    for (int s = 256; s; s >>= 1) {
        if (tid < s) sred[tid] += sred[tid + s];
        __syncthreads();
    }
    float E = sred[0]; __syncthreads();

    float wk = e / E;

    // exclusive popcount prefix over the 128 mask words (warp 0)
    if (tid < 32) {
        const unsigned FULL = 0xffffffffu;
        int b = tid * 4;
        int c0 = __popc(mask[b]);
        int c1 = __popc(mask[b + 1]);
        int c2 = __popc(mask[b + 2]);
        int c3 = __popc(mask[b + 3]);
        int tot = c0 + c1 + c2 + c3;
        int run = tot;
        #pragma unroll
        for (int off = 1; off < 32; off <<= 1) {
            int t = __shfl_up_sync(FULL, run, off);
            if (tid >= off) run += t;
        }
        int excl = run - tot;
        wordpfx[b]     = excl;
        wordpfx[b + 1] = excl + c0;
        wordpfx[b + 2] = excl + c0 + c1;
        wordpfx[b + 3] = excl + c0 + c1 + c2;
    }

    // ssum = sum of normalized scores (matches reference recompute)
    sred[tid] = (tid < KEL) ? wk : 0.0f; __syncthreads();
    #pragma unroll
    for (int s = 256; s; s >>= 1) {
        if (tid < s) sred[tid] += sred[tid + s];
        __syncthreads();
    }
    if (tid == 0) {
        float ssum = sred[0];
        g_scalars[0] = ssum;
        g_scalars[1] = 1.0f / (ssum + 1e-9f);
    }

    // scatter (idx, w) to its index-sorted position; pad the rest
    if (tid < KEL) {
        int word = idx >> 5, bit = idx & 31;
        int pos = wordpfx[word] + __popc(mask[word] & ((1u << bit) - 1u));
        g_sidx[pos] = idx;
        g_sw[pos]   = wk;
    } else {
        g_sw[tid]   = 0.0f;   // slots KEL..511: zero weight
        g_sidx[tid] = 0;
    }
}

// =====================================================================
// Kernel D: elite-gathered weighted mean/std per (t, a). One block per t,
// 1024 threads. VECTORIZED gather: each warp owns 16 sorted elites; per
// iteration the 32 lanes issue one LDG.128 covering 4 elite rows
// (lane>>3 = elite-in-group, (lane&7)*4 = a-quad). 4 LDG.128/thread
// (vs 13 scalar LDGs) -> all loads genuinely in flight within 32 regs.
// =====================================================================
__global__ void __launch_bounds__(1024) stats_kernel(
    const float* __restrict__ noise,   // [T, P, A]
    const float* __restrict__ means,   // [T, 1, A]
    const float* __restrict__ stds,    // [T, 1, A]
    float* __restrict__ out)           // [2, T, 1, A]
{
    const unsigned FULL = 0xffffffffu;
    int t    = blockIdx.x;
    int lane = threadIdx.x & 31;
    int warp = threadIdx.x >> 5;       // 0..31

    __shared__ float sw[KPAD];
    __shared__ int   si[KPAD];
    __shared__ float red1[32][33];
    __shared__ float red2[32][33];

    if (threadIdx.x < KPAD) {
        sw[threadIdx.x] = g_sw[threadIdx.x];
        si[threadIdx.x] = g_sidx[threadIdx.x];
    }
    __syncthreads();

    int e  = lane >> 3;          // elite-in-group: 0..3
    int a4 = (lane & 7) * 4;     // a-quad base: 0,4,..,28

    float4 mean4 = *(const float4*)(means + t * AA + a4);
    float4 std4  = *(const float4*)(stds  + t * AA + a4);
    const float* nbase = noise + (size_t)t * PN * AA;

    float S1x = 0.f, S1y = 0.f, S1z = 0.f, S1w = 0.f;
    float S2x = 0.f, S2y = 0.f, S2z = 0.f, S2w = 0.f;

    int k0 = warp * 16;
    #pragma unroll
    for (int it = 0; it < 4; it++) {
        int k  = k0 + it * 4 + e;
        float wk = sw[k];
        int   p  = si[k];
        float4 x = __ldg((const float4*)(nbase + p * AA + a4));

        float xx = fminf(fmaxf(fmaf(std4.x, x.x, mean4.x), -1.f), 1.f);
        float xy = fminf(fmaxf(fmaf(std4.y, x.y, mean4.y), -1.f), 1.f);
        float xz = fminf(fmaxf(fmaf(std4.z, x.z, mean4.z), -1.f), 1.f);
        float xw = fminf(fmaxf(fmaf(std4.w, x.w, mean4.w), -1.f), 1.f);

        S1x += wk * xx;  S2x += wk * xx * xx;
        S1y += wk * xy;  S2y += wk * xy * xy;
        S1z += wk * xz;  S2z += wk * xz * xz;
        S1w += wk * xw;  S2w += wk * xw * xw;
    }

    // reduce across the 4 elite-groups (lanes l, l+8, l+16, l+24)
    #pragma unroll
    for (int off = 16; off >= 8; off >>= 1) {
        S1x += __shfl_down_sync(FULL, S1x, off);
        S1y += __shfl_down_sync(FULL, S1y, off);
        S1z += __shfl_down_sync(FULL, S1z, off);
        S1w += __shfl_down_sync(FULL, S1w, off);
        S2x += __shfl_down_sync(FULL, S2x, off);
        S2y += __shfl_down_sync(FULL, S2y, off);
        S2z += __shfl_down_sync(FULL, S2z, off);
        S2w += __shfl_down_sync(FULL, S2w, off);
    }

    if (lane < 8) {
        red1[warp][a4 + 0] = S1x;  red2[warp][a4 + 0] = S2x;
        red1[warp][a4 + 1] = S1y;  red2[warp][a4 + 1] = S2y;
        red1[warp][a4 + 2] = S1z;  red2[warp][a4 + 2] = S2z;
        red1[warp][a4 + 3] = S1w;  red2[warp][a4 + 3] = S2w;
    }
    __syncthreads();

    if (warp == 0) {
        float s1 = 0.0f, s2 = 0.0f;
        #pragma unroll
        for (int i = 0; i < 32; i++) { s1 += red1[i][lane]; s2 += red2[i][lane]; }

        float mean_ta = means[t * AA + lane];
        float W     = g_scalars[0];
        float recip = g_scalars[1];
        float mu  = s1 * recip;
        float var = fmaxf((s2 - 2.0f * mu * s1 + mu * mu * W) * recip, 0.0f);
        float sd  = fminf(fmaxf(sqrtf(var), 0.05f), 1.0f);

        out[t * AA + lane]           = 0.1f * mean_ta + 0.9f * mu;  // means_new
        out[TT * AA + t * AA + lane] = sd;                          // _std
    }
}

// =====================================================================
extern "C" void kernel_launch(void* const* d_in, const int* in_sizes, int n_in,
                              void* d_out, int out_size) {
    const float* obs   = (const float*)d_in[0];  // [P, T, T]
    const float* means = (const float*)d_in[1];  // [T, 1, A]
    const float* stds  = (const float*)d_in[2];  // [T, 1, A]
    const float* noise = (const float*)d_in[3];  // [T, P, A]
    float* out = (float*)d_out;                  // [2, T, 1, A]

    dtw_kernel  <<<PN / 8, 256>>>(obs);    // 4096 warps, 1 problem/warp
    rank_kernel <<<PN / 32, 256>>>();
    score_kernel<<<1, 512>>>();
    stats_kernel<<<TT, 1024>>>(noise, means, stds, out);
}

// round 16
// speedup vs baseline: 1.0100x; 1.0100x over previous
#include <cuda_runtime.h>
#include <math.h>

// Problem constants
#define PN   4096
#define TT   128
#define AA   32
#define KEL  409          // int(4096 * 0.1)
#define KPAD 512          // 32 warps * 16 elites, zero-weight padded
#define INFF 1e30f

// ---------------- scratch (no allocations allowed) ----------------
__device__ float g_dists[PN];
__device__ int   g_eidx[KEL];      // elite indices, rank order (top_k order)
__device__ float g_edist[KEL];     // elite dists, rank order
__device__ int   g_sidx[KPAD];     // elite indices sorted ASCENDING BY INDEX
__device__ float g_sw[KPAD];       // weights permuted to match g_sidx
__device__ float g_scalars[2];     // [0] = ssum, [1] = 1/(ssum+1e-9)

// =====================================================================
// Kernel A: DTW min-plus DP, one warp per problem. Inner loop is the
// frozen R13 version (every structural variant regressed). This round's
// single change: 64-thread CTAs (2 warps) instead of 256 — 2048 CTAs
// give 8x finer CTA-balance granularity, eliminating the wave-
// quantization tail of 512x8-warp CTAs at 3-CTA/SM occupancy, and
// raise resident warps/SM under the register budget.
// =====================================================================
__global__ void __launch_bounds__(64) dtw_kernel(const float* __restrict__ obs) {
    const unsigned FULL = 0xffffffffu;
    int warpId = (blockIdx.x * blockDim.x + threadIdx.x) >> 5;
    int lane   = threadIdx.x & 31;
    if (warpId >= PN) return;

    const float4* cbase = (const float4*)(obs + (size_t)warpId * TT * TT);

    float v0 = INFF, v1 = INFF, v2 = INFF, v3 = INFF;
    float carry = 0.0f;

    float4 c0 = __ldcs(cbase + lane);
    float s0 = c0.x;
    float s1 = s0 + c0.y;
    float s2 = s1 + c0.z;
    float s3 = s2 + c0.w;
    {
        float sum = s3;
        #pragma unroll
        for (int off = 1; off < 32; off <<= 1) {
            float t = __shfl_up_sync(FULL, sum, off);
            if (lane >= off) sum += t;
        }
        float base0 = sum - s3;
        s0 += base0; s1 += base0; s2 += base0; s3 += base0;
        c0.x = base0;
    }
    float base = c0.x;

    float4 cn = __ldcs(cbase + 32 + lane);

    #pragma unroll 2
    for (int i = 0; i < TT; i++) {
        int nl = (i + 2 < TT) ? (i + 2) : (TT - 1);
        float4 cf = __ldcs(cbase + nl * 32 + lane);

        float ns0 = cn.x;
        float ns1 = ns0 + cn.y;
        float ns2 = ns1 + cn.z;
        float ns3 = ns2 + cn.w;

        float up  = __shfl_up_sync(FULL, v3, 1);
        float sh0 = (lane == 0) ? carry : up;

        float m0 = fminf(v0, sh0);
        float m1 = fminf(v1, v0);
        float m2 = fminf(v2, v1);
        float m3 = fminf(v3, v2);

        float t0 = m0 - base;
        float t1 = m1 - s0;
        float t2 = m2 - s1;
        float t3 = m3 - s2;

        float p0 = t0;
        float p1 = fminf(p0, t1);
        float p2 = fminf(p1, t2);
        float p3 = fminf(p2, t3);

        float nsum = ns3;
        float mn   = p3;
        #pragma unroll
        for (int off = 1; off < 32; off <<= 1) {
            float ta = __shfl_up_sync(FULL, nsum, off);
            float tb = __shfl_up_sync(FULL, mn, off);
            if (lane >= off) {
                nsum += ta;
                mn    = fminf(mn, tb);
            }
        }

        float ex = __shfl_up_sync(FULL, mn, 1);
        if (lane == 0) ex = INFF;

        float nbase = nsum - ns3;

        v0 = s0 + fminf(p0, ex);
        v1 = s1 + fminf(p1, ex);
        v2 = s2 + fminf(p2, ex);
        v3 = s3 + fminf(p3, ex);

        base = nbase;
        s0 = ns0 + nbase;
        s1 = ns1 + nbase;
        s2 = ns2 + nbase;
        s3 = ns3 + nbase;
        carry = INFF;
        cn = cf;
    }

    if (lane == 31) g_dists[warpId] = v3;
}

// =====================================================================
// Kernel B: exact top-K selection via rank counting (unchanged).
// =====================================================================
__global__ void __launch_bounds__(256) rank_kernel() {
    __shared__ float sd[PN];
    for (int i = threadIdx.x; i < PN; i += blockDim.x) sd[i] = g_dists[i];
    __syncthreads();

    int warp = threadIdx.x >> 5;
    int lane = threadIdx.x & 31;

    #pragma unroll
    for (int e = 0; e < 4; e++) {
        int p = blockIdx.x * 32 + warp * 4 + e;
        float d = sd[p];
        int cnt = 0;
        #pragma unroll 4
        for (int j = lane; j < PN; j += 32) {
            float dj = sd[j];
            cnt += (dj < d) || (dj == d && j < p);
        }
        #pragma unroll
        for (int off = 16; off; off >>= 1)
            cnt += __shfl_down_sync(0xffffffffu, cnt, off);
        if (lane == 0 && cnt < KEL) {
            g_eidx[cnt]  = p;
            g_edist[cnt] = d;
        }
    }
}

// =====================================================================
// Kernel C: softmax elite scores + INDEX-SORTED re-emission (padded to
// 512 zero-weight slots so stats warps get exactly 16 elites each).
// =====================================================================
__global__ void __launch_bounds__(512) score_kernel() {
    __shared__ float sred[512];
    __shared__ unsigned mask[PN / 32];   // 128 words
    __shared__ int wordpfx[PN / 32];     // exclusive popcount prefix
    int tid = threadIdx.x;

    float d = (tid < KEL) ? g_edist[tid] : INFF;
    int   idx = (tid < KEL) ? g_eidx[tid] : 0;

    if (tid < PN / 32) mask[tid] = 0u;

    // min reduce
    sred[tid] = d; __syncthreads();
    #pragma unroll
    for (int s = 256; s; s >>= 1) {
        if (tid < s) sred[tid] = fminf(sred[tid], sred[tid + s]);
        __syncthreads();
    }
    float mind = sred[0]; __syncthreads();

    float e = (tid < KEL) ? expf(0.5f * (mind - d)) : 0.0f;

    // sum reduce of e; also build the elite index bitmask
    sred[tid] = e;
    if (tid < KEL) atomicOr(&mask[idx >> 5], 1u << (idx & 31));
    __syncthreads();
    #pragma unroll
    for (int s = 256; s; s >>= 1) {
        if (tid < s) sred[tid] += sred[tid + s];
        __syncthreads();
    }
    float E = sred[0]; __syncthreads();

    float wk = e / E;

    // exclusive popcount prefix over the 128 mask words (warp 0)
    if (tid < 32) {
        const unsigned FULL = 0xffffffffu;
        int b = tid * 4;
        int c0 = __popc(mask[b]);
        int c1 = __popc(mask[b + 1]);
        int c2 = __popc(mask[b + 2]);
        int c3 = __popc(mask[b + 3]);
        int tot = c0 + c1 + c2 + c3;
        int run = tot;
        #pragma unroll
        for (int off = 1; off < 32; off <<= 1) {
            int t = __shfl_up_sync(FULL, run, off);
            if (tid >= off) run += t;
        }
        int excl = run - tot;
        wordpfx[b]     = excl;
        wordpfx[b + 1] = excl + c0;
        wordpfx[b + 2] = excl + c0 + c1;
        wordpfx[b + 3] = excl + c0 + c1 + c2;
    }

    // ssum = sum of normalized scores (matches reference recompute)
    sred[tid] = (tid < KEL) ? wk : 0.0f; __syncthreads();
    #pragma unroll
    for (int s = 256; s; s >>= 1) {
        if (tid < s) sred[tid] += sred[tid + s];
        __syncthreads();
    }
    if (tid == 0) {
        float ssum = sred[0];
        g_scalars[0] = ssum;
        g_scalars[1] = 1.0f / (ssum + 1e-9f);
    }

    // scatter (idx, w) to its index-sorted position; pad the rest
    if (tid < KEL) {
        int word = idx >> 5, bit = idx & 31;
        int pos = wordpfx[word] + __popc(mask[word] & ((1u << bit) - 1u));
        g_sidx[pos] = idx;
        g_sw[pos]   = wk;
    } else {
        g_sw[tid]   = 0.0f;   // slots KEL..511: zero weight
        g_sidx[tid] = 0;
    }
}

// =====================================================================
// Kernel D: elite-gathered weighted mean/std per (t, a). One block per t,
// 1024 threads, float4 gathers (unchanged from R15).
// =====================================================================
__global__ void __launch_bounds__(1024) stats_kernel(
    const float* __restrict__ noise,   // [T, P, A]
    const float* __restrict__ means,   // [T, 1, A]
    const float* __restrict__ stds,    // [T, 1, A]
    float* __restrict__ out)           // [2, T, 1, A]
{
    const unsigned FULL = 0xffffffffu;
    int t    = blockIdx.x;
    int lane = threadIdx.x & 31;
    int warp = threadIdx.x >> 5;       // 0..31

    __shared__ float sw[KPAD];
    __shared__ int   si[KPAD];
    __shared__ float red1[32][33];
    __shared__ float red2[32][33];

    if (threadIdx.x < KPAD) {
        sw[threadIdx.x] = g_sw[threadIdx.x];
        si[threadIdx.x] = g_sidx[threadIdx.x];
    }
    __syncthreads();

    int e  = lane >> 3;          // elite-in-group: 0..3
    int a4 = (lane & 7) * 4;     // a-quad base: 0,4,..,28

    float4 mean4 = *(const float4*)(means + t * AA + a4);
    float4 std4  = *(const float4*)(stds  + t * AA + a4);
    const float* nbase = noise + (size_t)t * PN * AA;

    float S1x = 0.f, S1y = 0.f, S1z = 0.f, S1w = 0.f;
    float S2x = 0.f, S2y = 0.f, S2z = 0.f, S2w = 0.f;

    int k0 = warp * 16;
    #pragma unroll
    for (int it = 0; it < 4; it++) {
        int k  = k0 + it * 4 + e;
        float wk = sw[k];
        int   p  = si[k];
        float4 x = __ldg((const float4*)(nbase + p * AA + a4));

        float xx = fminf(fmaxf(fmaf(std4.x, x.x, mean4.x), -1.f), 1.f);
        float xy = fminf(fmaxf(fmaf(std4.y, x.y, mean4.y), -1.f), 1.f);
        float xz = fminf(fmaxf(fmaf(std4.z, x.z, mean4.z), -1.f), 1.f);
        float xw = fminf(fmaxf(fmaf(std4.w, x.w, mean4.w), -1.f), 1.f);

        S1x += wk * xx;  S2x += wk * xx * xx;
        S1y += wk * xy;  S2y += wk * xy * xy;
        S1z += wk * xz;  S2z += wk * xz * xz;
        S1w += wk * xw;  S2w += wk * xw * xw;
    }

    // reduce across the 4 elite-groups (lanes l, l+8, l+16, l+24)
    #pragma unroll
    for (int off = 16; off >= 8; off >>= 1) {
        S1x += __shfl_down_sync(FULL, S1x, off);
        S1y += __shfl_down_sync(FULL, S1y, off);
        S1z += __shfl_down_sync(FULL, S1z, off);
        S1w += __shfl_down_sync(FULL, S1w, off);
        S2x += __shfl_down_sync(FULL, S2x, off);
        S2y += __shfl_down_sync(FULL, S2y, off);
        S2z += __shfl_down_sync(FULL, S2z, off);
        S2w += __shfl_down_sync(FULL, S2w, off);
    }

    if (lane < 8) {
        red1[warp][a4 + 0] = S1x;  red2[warp][a4 + 0] = S2x;
        red1[warp][a4 + 1] = S1y;  red2[warp][a4 + 1] = S2y;
        red1[warp][a4 + 2] = S1z;  red2[warp][a4 + 2] = S2z;
        red1[warp][a4 + 3] = S1w;  red2[warp][a4 + 3] = S2w;
    }
    __syncthreads();

    if (warp == 0) {
        float s1 = 0.0f, s2 = 0.0f;
        #pragma unroll
        for (int i = 0; i < 32; i++) { s1 += red1[i][lane]; s2 += red2[i][lane]; }

        float mean_ta = means[t * AA + lane];
        float W     = g_scalars[0];
        float recip = g_scalars[1];
        float mu  = s1 * recip;
        float var = fmaxf((s2 - 2.0f * mu * s1 + mu * mu * W) * recip, 0.0f);
        float sd  = fminf(fmaxf(sqrtf(var), 0.05f), 1.0f);

        out[t * AA + lane]           = 0.1f * mean_ta + 0.9f * mu;  // means_new
        out[TT * AA + t * AA + lane] = sd;                          // _std
    }
}

// =====================================================================
extern "C" void kernel_launch(void* const* d_in, const int* in_sizes, int n_in,
                              void* d_out, int out_size) {
    const float* obs   = (const float*)d_in[0];  // [P, T, T]
    const float* means = (const float*)d_in[1];  // [T, 1, A]
    const float* stds  = (const float*)d_in[2];  // [T, 1, A]
    const float* noise = (const float*)d_in[3];  // [T, P, A]
    float* out = (float*)d_out;                  // [2, T, 1, A]

    dtw_kernel  <<<PN / 2, 64>>>(obs);     // 2048 CTAs x 2 warps: fine-grain balance
    rank_kernel <<<PN / 32, 256>>>();
    score_kernel<<<1, 512>>>();
    stats_kernel<<<TT, 1024>>>(noise, means, stds, out);
}